// round 6
// baseline (speedup 1.0000x reference)
#include <cuda_runtime.h>
#include <cuda_bf16.h>

#define KDIM 64
#define MAXB 1024
#define PF   4   // prefetch depth (steps)
#define WPB  8   // warps (batches) per block

__device__ float g_partial[MAXB];

typedef unsigned long long ull;

__device__ __forceinline__ void fma2(ull& acc, ull a, ull b) {
    asm("fma.rn.f32x2 %0, %1, %2, %3;" : "=l"(acc) : "l"(a), "l"(b), "l"(acc));
}
__device__ __forceinline__ void add2(ull& d, ull a, ull b) {
    asm("add.rn.f32x2 %0, %1, %2;" : "=l"(d) : "l"(a), "l"(b));
}

// ONE WARP PER BATCH, 8 warps per block (2 warps/SMSP for latency hiding).
// Lane l owns columns j0=2l, j1=2l+1.
// Linear-space recursion with exact power-of-2 renorm:
//   a[t+1][j] = ( sum_i a[t][i] * E[i][j] ) * 2^(127-e) * exp(emit[t][j])
// E = exp(trans) in registers (64 packed f32x2 pairs -> 128 regs).
// Per step: STS.64 + __syncwarp + 16 broadcast LDS.128; no __syncthreads.
// All global traffic (emissions, labels, gold transition values) prefetched
// PF steps ahead; renorm pivot via shfl of lane 0 (off the critical chain).
__global__ __launch_bounds__(32 * WPB, 1)
void crf_forward_kernel(const float* __restrict__ emis,
                        const float* __restrict__ trans,
                        const float* __restrict__ start_t,
                        const float* __restrict__ end_t,
                        const int*  __restrict__ labels,
                        const int*  __restrict__ sent_len,
                        int T)
{
    const int warp = threadIdx.x >> 5;
    const int lane = threadIdx.x & 31;
    const int b    = blockIdx.x * WPB + warp;
    const int j0   = 2 * lane;
    const int j1   = j0 + 1;
    const int L    = sent_len[b];
    const float* em  = emis   + (size_t)b * T * KDIM;
    const int*   lab = labels + (size_t)b * T;

    __shared__ __align__(16) float sa_all[WPB][2][KDIM];
    float (*sa)[KDIM] = sa_all[warp];

    // E pairs over i for the two owned columns: 64 ull = 128 regs
    ull Epk0[KDIM / 2], Epk1[KDIM / 2];
#pragma unroll
    for (int i2 = 0; i2 < KDIM / 2; ++i2) {
        const float a00 = __expf(trans[(2 * i2)     * KDIM + j0]);
        const float a10 = __expf(trans[(2 * i2 + 1) * KDIM + j0]);
        const float a01 = __expf(trans[(2 * i2)     * KDIM + j1]);
        const float a11 = __expf(trans[(2 * i2 + 1) * KDIM + j1]);
        Epk0[i2] = (ull)__float_as_uint(a00) | ((ull)__float_as_uint(a10) << 32);
        Epk1[i2] = (ull)__float_as_uint(a01) | ((ull)__float_as_uint(a11) << 32);
    }

    // t = 0
    const float2 st  = ((const float2*)start_t)[lane];
    const float2 em0 = ((const float2*)em)[lane];
    const float l0x = st.x + em0.x;
    const float l0y = st.y + em0.y;
    float ax = __expf(l0x);
    float ay = __expf(l0y);
    int   Stot = 0;
    float gold_emit  = 0.0f;   // per-lane masked emission (+start/end) terms
    float gold_trans = 0.0f;   // uniform across lanes (broadcast tv)
    int   lab_last = lab[0];
    if (j0 == lab_last) gold_emit = l0x;
    if (j1 == lab_last) gold_emit = l0y;

    // prefetch rings for steps t = 1..PF
    float2 er[PF], Pr[PF];
    float  tvr[PF];
    int    lbr[PF];
    int lab_roll = lab_last;                  // lab[t-1] rolling value
#pragma unroll
    for (int k = 0; k < PF; ++k) {
        int tt = 1 + k; if (tt > T - 1) tt = T - 1;
        const float2 ee = ((const float2*)(em + (size_t)tt * KDIM))[lane];
        er[k] = ee;
        Pr[k] = make_float2(__expf(ee.x), __expf(ee.y));
        const int l1 = lab[tt];
        lbr[k] = l1;
        tvr[k] = trans[lab_roll * KDIM + l1];
        lab_roll = l1;
    }

    int buf = 0;
    auto step = [&](float2 P, float2 eraw, int labt, float tvv) {
        // pivot from lane 0's register (off-chain)
        const float piv = __shfl_sync(0xffffffffu, ax, 0);
        ((float2*)sa[buf])[lane] = make_float2(ax, ay);
        __syncwarp();
        const int   e   = (int)((__float_as_uint(piv) >> 23) & 0xffu);
        const float scl = __uint_as_float((unsigned)(254 - e) << 23); // 2^(127-e)
        Stot += e - 127;
        // gold terms (all in registers)
        if (j0 == labt) gold_emit += eraw.x;
        if (j1 == labt) gold_emit += eraw.y;
        gold_trans += tvv;
        lab_last = labt;
        // two dots (columns j0, j1) sharing the sa loads
        ull b0 = 0ull, b1 = 0ull, b2 = 0ull, b3 = 0ull;
        ull c0 = 0ull, c1 = 0ull, c2 = 0ull, c3 = 0ull;
        const ulonglong2* sv = (const ulonglong2*)sa[buf];
#pragma unroll
        for (int q = 0; q < 8; ++q) {
            const ulonglong2 v0 = sv[2 * q];
            const ulonglong2 v1 = sv[2 * q + 1];
            fma2(b0, v0.x, Epk0[4 * q + 0]);  fma2(c0, v0.x, Epk1[4 * q + 0]);
            fma2(b1, v0.y, Epk0[4 * q + 1]);  fma2(c1, v0.y, Epk1[4 * q + 1]);
            fma2(b2, v1.x, Epk0[4 * q + 2]);  fma2(c2, v1.x, Epk1[4 * q + 2]);
            fma2(b3, v1.y, Epk0[4 * q + 3]);  fma2(c3, v1.y, Epk1[4 * q + 3]);
        }
        add2(b0, b0, b1); add2(b2, b2, b3); add2(b0, b0, b2);
        add2(c0, c0, c1); add2(c2, c2, c3); add2(c0, c0, c2);
        const float d0 = __uint_as_float((unsigned)b0)
                       + __uint_as_float((unsigned)(b0 >> 32));
        const float d1 = __uint_as_float((unsigned)c0)
                       + __uint_as_float((unsigned)(c0 >> 32));
        ax = d0 * scl * P.x;
        ay = d1 * scl * P.y;
        buf ^= 1;
    };

    int t = 1;
    for (; t + PF <= L; t += PF) {
#pragma unroll
        for (int k = 0; k < PF; ++k) {
            const float2 Pc = Pr[k], ec = er[k];
            const float  tc = tvr[k];
            const int    lc = lbr[k];
            int tp = t + PF + k; if (tp > T - 1) tp = T - 1;
            const float2 ee = ((const float2*)(em + (size_t)tp * KDIM))[lane];
            er[k] = ee;
            Pr[k] = make_float2(__expf(ee.x), __expf(ee.y));
            const int l1 = lab[tp];
            lbr[k] = l1;
            tvr[k] = trans[lab_roll * KDIM + l1];   // garbage if clamped; never consumed
            lab_roll = l1;
            step(Pc, ec, lc, tc);
        }
    }
    for (int k = 0; t < L; ++t, ++k) {     // tail: ring already filled
        step(Pr[k], er[k], lbr[k], tvr[k]);
    }

    // gold end term + final logsumexp (linear space)
    {
        const float2 en = ((const float2*)end_t)[lane];
        if (j0 == lab_last) gold_emit += en.x;
        if (j1 == lab_last) gold_emit += en.y;
        float xs = ax * __expf(en.x) + ay * __expf(en.y);
        float gg = gold_emit;
#pragma unroll
        for (int o = 16; o; o >>= 1) {
            xs += __shfl_xor_sync(0xffffffffu, xs, o);
            gg += __shfl_xor_sync(0xffffffffu, gg, o);
        }
        if (lane == 0) {
            const float fwd = __logf(xs) + (float)Stot * 0.69314718055994530942f;
            g_partial[b] = fwd - (gg + gold_trans);
        }
    }
}

// Deterministic final reduction: out = sum(partial)/B
__global__ void crf_reduce_kernel(float* __restrict__ out, int B)
{
    __shared__ float ws[16];
    const int tid = threadIdx.x;
    float v = 0.0f;
    for (int i = tid; i < B; i += blockDim.x) v += g_partial[i];
#pragma unroll
    for (int o = 16; o; o >>= 1) v += __shfl_xor_sync(0xffffffffu, v, o);
    if ((tid & 31) == 0) ws[tid >> 5] = v;
    __syncthreads();
    if (tid < 16) {
        float u = (tid < (blockDim.x + 31) / 32) ? ws[tid] : 0.0f;
#pragma unroll
        for (int o = 8; o; o >>= 1) u += __shfl_xor_sync(0x0000ffffu, u, o);
        if (tid == 0) out[0] = u / (float)B;
    }
}

extern "C" void kernel_launch(void* const* d_in, const int* in_sizes, int n_in,
                              void* d_out, int out_size)
{
    const float* emis    = (const float*)d_in[0];
    const float* trans   = (const float*)d_in[1];
    const float* start_t = (const float*)d_in[2];
    const float* end_t   = (const float*)d_in[3];
    const int*   labels  = (const int*)d_in[4];
    const int*   slen    = (const int*)d_in[5];

    const int B = in_sizes[5];            // 512
    const int T = in_sizes[4] / B;        // 1024
    float* out = (float*)d_out;

    crf_forward_kernel<<<B / WPB, 32 * WPB>>>(emis, trans, start_t, end_t, labels, slen, T);
    crf_reduce_kernel<<<1, 512>>>(out, B);
}

// round 7
// speedup vs baseline: 1.0855x; 1.0855x over previous
#include <cuda_runtime.h>
#include <cuda_bf16.h>

#define KDIM 64
#define MAXB 1024
#define PF   4   // prefetch depth (steps)
#define WPB  4   // warps (batches) per block -> one warp per SMSP

__device__ float g_partial[MAXB];

typedef unsigned long long ull;

__device__ __forceinline__ void fma2(ull& acc, ull a, ull b) {
    asm("fma.rn.f32x2 %0, %1, %2, %3;" : "=l"(acc) : "l"(a), "l"(b), "l"(acc));
}
__device__ __forceinline__ void add2(ull& d, ull a, ull b) {
    asm("add.rn.f32x2 %0, %1, %2;" : "=l"(d) : "l"(a), "l"(b));
}

// ONE WARP PER BATCH, 4 warps per block: warp w -> SMSP w (wid%4), so every
// warp owns a private scheduler and the grid (128 blocks) covers 128 SMs.
// Lane l owns columns j0=2l, j1=2l+1.
// Linear-space recursion with exact power-of-2 renorm:
//   a[t+1][j] = ( sum_i a[t][i] * E[i][j] ) * 2^(127-e) * exp(emit[t][j])
// E = exp(trans) in registers (64 packed f32x2 pairs -> 128 regs).
// Per step: STS.64 + __syncwarp + 16 broadcast LDS.128; no __syncthreads.
// All global traffic (emissions, labels, gold transition values) prefetched
// PF steps ahead; renorm pivot via shfl of lane 0 (off the critical chain).
__global__ __launch_bounds__(32 * WPB, 1)
void crf_forward_kernel(const float* __restrict__ emis,
                        const float* __restrict__ trans,
                        const float* __restrict__ start_t,
                        const float* __restrict__ end_t,
                        const int*  __restrict__ labels,
                        const int*  __restrict__ sent_len,
                        int T)
{
    const int warp = threadIdx.x >> 5;
    const int lane = threadIdx.x & 31;
    const int b    = blockIdx.x * WPB + warp;
    const int j0   = 2 * lane;
    const int j1   = j0 + 1;
    const int L    = sent_len[b];
    const float* em  = emis   + (size_t)b * T * KDIM;
    const int*   lab = labels + (size_t)b * T;

    __shared__ __align__(16) float sa_all[WPB][2][KDIM];
    float (*sa)[KDIM] = sa_all[warp];

    // E pairs over i for the two owned columns: 64 ull = 128 regs
    ull Epk0[KDIM / 2], Epk1[KDIM / 2];
#pragma unroll
    for (int i2 = 0; i2 < KDIM / 2; ++i2) {
        const float a00 = __expf(trans[(2 * i2)     * KDIM + j0]);
        const float a10 = __expf(trans[(2 * i2 + 1) * KDIM + j0]);
        const float a01 = __expf(trans[(2 * i2)     * KDIM + j1]);
        const float a11 = __expf(trans[(2 * i2 + 1) * KDIM + j1]);
        Epk0[i2] = (ull)__float_as_uint(a00) | ((ull)__float_as_uint(a10) << 32);
        Epk1[i2] = (ull)__float_as_uint(a01) | ((ull)__float_as_uint(a11) << 32);
    }

    // t = 0
    const float2 st  = ((const float2*)start_t)[lane];
    const float2 em0 = ((const float2*)em)[lane];
    const float l0x = st.x + em0.x;
    const float l0y = st.y + em0.y;
    float ax = __expf(l0x);
    float ay = __expf(l0y);
    int   Stot = 0;
    float gold_emit  = 0.0f;   // per-lane masked emission (+start/end) terms
    float gold_trans = 0.0f;   // uniform across lanes (broadcast tv)
    int   lab_last = lab[0];
    if (j0 == lab_last) gold_emit = l0x;
    if (j1 == lab_last) gold_emit = l0y;

    // prefetch rings for steps t = 1..PF
    float2 er[PF], Pr[PF];
    float  tvr[PF];
    int    lbr[PF];
    int lab_roll = lab_last;                  // lab[t-1] rolling value
#pragma unroll
    for (int k = 0; k < PF; ++k) {
        int tt = 1 + k; if (tt > T - 1) tt = T - 1;
        const float2 ee = ((const float2*)(em + (size_t)tt * KDIM))[lane];
        er[k] = ee;
        Pr[k] = make_float2(__expf(ee.x), __expf(ee.y));
        const int l1 = lab[tt];
        lbr[k] = l1;
        tvr[k] = trans[lab_roll * KDIM + l1];
        lab_roll = l1;
    }

    int buf = 0;
    auto step = [&](float2 P, float2 eraw, int labt, float tvv) {
        // pivot from lane 0's register (off-chain)
        const float piv = __shfl_sync(0xffffffffu, ax, 0);
        ((float2*)sa[buf])[lane] = make_float2(ax, ay);
        __syncwarp();
        const int   e   = (int)((__float_as_uint(piv) >> 23) & 0xffu);
        const float scl = __uint_as_float((unsigned)(254 - e) << 23); // 2^(127-e)
        Stot += e - 127;
        // gold terms (all in registers)
        if (j0 == labt) gold_emit += eraw.x;
        if (j1 == labt) gold_emit += eraw.y;
        gold_trans += tvv;
        lab_last = labt;
        // two dots (columns j0, j1) sharing the sa loads
        ull b0 = 0ull, b1 = 0ull, b2 = 0ull, b3 = 0ull;
        ull c0 = 0ull, c1 = 0ull, c2 = 0ull, c3 = 0ull;
        const ulonglong2* sv = (const ulonglong2*)sa[buf];
#pragma unroll
        for (int q = 0; q < 8; ++q) {
            const ulonglong2 v0 = sv[2 * q];
            const ulonglong2 v1 = sv[2 * q + 1];
            fma2(b0, v0.x, Epk0[4 * q + 0]);  fma2(c0, v0.x, Epk1[4 * q + 0]);
            fma2(b1, v0.y, Epk0[4 * q + 1]);  fma2(c1, v0.y, Epk1[4 * q + 1]);
            fma2(b2, v1.x, Epk0[4 * q + 2]);  fma2(c2, v1.x, Epk1[4 * q + 2]);
            fma2(b3, v1.y, Epk0[4 * q + 3]);  fma2(c3, v1.y, Epk1[4 * q + 3]);
        }
        add2(b0, b0, b1); add2(b2, b2, b3); add2(b0, b0, b2);
        add2(c0, c0, c1); add2(c2, c2, c3); add2(c0, c0, c2);
        const float d0 = __uint_as_float((unsigned)b0)
                       + __uint_as_float((unsigned)(b0 >> 32));
        const float d1 = __uint_as_float((unsigned)c0)
                       + __uint_as_float((unsigned)(c0 >> 32));
        ax = d0 * scl * P.x;
        ay = d1 * scl * P.y;
        buf ^= 1;
    };

    int t = 1;
    for (; t + PF <= L; t += PF) {
#pragma unroll
        for (int k = 0; k < PF; ++k) {
            const float2 Pc = Pr[k], ec = er[k];
            const float  tc = tvr[k];
            const int    lc = lbr[k];
            int tp = t + PF + k; if (tp > T - 1) tp = T - 1;
            const float2 ee = ((const float2*)(em + (size_t)tp * KDIM))[lane];
            er[k] = ee;
            Pr[k] = make_float2(__expf(ee.x), __expf(ee.y));
            const int l1 = lab[tp];
            lbr[k] = l1;
            tvr[k] = trans[lab_roll * KDIM + l1];   // garbage if clamped; never consumed
            lab_roll = l1;
            step(Pc, ec, lc, tc);
        }
    }
    for (int k = 0; t < L; ++t, ++k) {     // tail: ring already filled
        step(Pr[k], er[k], lbr[k], tvr[k]);
    }

    // gold end term + final logsumexp (linear space)
    {
        const float2 en = ((const float2*)end_t)[lane];
        if (j0 == lab_last) gold_emit += en.x;
        if (j1 == lab_last) gold_emit += en.y;
        float xs = ax * __expf(en.x) + ay * __expf(en.y);
        float gg = gold_emit;
#pragma unroll
        for (int o = 16; o; o >>= 1) {
            xs += __shfl_xor_sync(0xffffffffu, xs, o);
            gg += __shfl_xor_sync(0xffffffffu, gg, o);
        }
        if (lane == 0) {
            const float fwd = __logf(xs) + (float)Stot * 0.69314718055994530942f;
            g_partial[b] = fwd - (gg + gold_trans);
        }
    }
}

// Deterministic final reduction: out = sum(partial)/B
__global__ void crf_reduce_kernel(float* __restrict__ out, int B)
{
    __shared__ float ws[16];
    const int tid = threadIdx.x;
    float v = 0.0f;
    for (int i = tid; i < B; i += blockDim.x) v += g_partial[i];
#pragma unroll
    for (int o = 16; o; o >>= 1) v += __shfl_xor_sync(0xffffffffu, v, o);
    if ((tid & 31) == 0) ws[tid >> 5] = v;
    __syncthreads();
    if (tid < 16) {
        float u = (tid < (blockDim.x + 31) / 32) ? ws[tid] : 0.0f;
#pragma unroll
        for (int o = 8; o; o >>= 1) u += __shfl_xor_sync(0x0000ffffu, u, o);
        if (tid == 0) out[0] = u / (float)B;
    }
}

extern "C" void kernel_launch(void* const* d_in, const int* in_sizes, int n_in,
                              void* d_out, int out_size)
{
    const float* emis    = (const float*)d_in[0];
    const float* trans   = (const float*)d_in[1];
    const float* start_t = (const float*)d_in[2];
    const float* end_t   = (const float*)d_in[3];
    const int*   labels  = (const int*)d_in[4];
    const int*   slen    = (const int*)d_in[5];

    const int B = in_sizes[5];            // 512
    const int T = in_sizes[4] / B;        // 1024
    float* out = (float*)d_out;

    crf_forward_kernel<<<B / WPB, 32 * WPB>>>(emis, trans, start_t, end_t, labels, slen, T);
    crf_reduce_kernel<<<1, 512>>>(out, B);
}

// round 8
// speedup vs baseline: 1.7437x; 1.6064x over previous
#include <cuda_runtime.h>
#include <cuda_bf16.h>

#define KDIM 64
#define MAXB 1024
#define MAXT 2048
#define PF   4   // prefetch depth (steps)

__device__ float g_fwd[MAXB];
__device__ float g_gold[MAXB];
__device__ float g_gs[512 * 1024];   // per-(b,t) gold contributions (B*T)

typedef unsigned long long ull;

__device__ __forceinline__ void fma2(ull& acc, ull a, ull b) {
    asm("fma.rn.f32x2 %0, %1, %2, %3;" : "=l"(acc) : "l"(a), "l"(b), "l"(acc));
}
__device__ __forceinline__ void add2(ull& d, ull a, ull b) {
    asm("add.rn.f32x2 %0, %1, %2;" : "=l"(d) : "l"(a), "l"(b));
}

// ---------------- gold score: fully parallel over (b, t) ----------------
__global__ void crf_gold_prepass(const float* __restrict__ emis,
                                 const float* __restrict__ trans,
                                 const float* __restrict__ start_t,
                                 const int*  __restrict__ labels,
                                 int B, int T)
{
    const int idx = blockIdx.x * blockDim.x + threadIdx.x;
    if (idx >= B * T) return;
    const int t = idx % T;
    const int lab_t = labels[idx];
    float v = emis[(size_t)idx * KDIM + lab_t];
    if (t == 0) v += start_t[lab_t];
    else        v += trans[labels[idx - 1] * KDIM + lab_t];
    g_gs[idx] = v;
}

// one warp per batch: gold[b] = sum_{t<L} gs[b,t] + end[lab[L-1]]
__global__ void crf_gold_reduce(const float* __restrict__ end_t,
                                const int*  __restrict__ labels,
                                const int*  __restrict__ sent_len,
                                int T)
{
    const int wid  = threadIdx.x >> 5;
    const int lane = threadIdx.x & 31;
    const int b    = blockIdx.x * (blockDim.x >> 5) + wid;
    const int L    = sent_len[b];
    const float* gs = g_gs + (size_t)b * T;
    float s = 0.0f;
    for (int t = lane; t < L; t += 32) s += gs[t];
#pragma unroll
    for (int o = 16; o; o >>= 1) s += __shfl_xor_sync(0xffffffffu, s, o);
    if (lane == 0)
        g_gold[b] = s + end_t[labels[(size_t)b * T + L - 1]];
}

// ---------------- forward recursion: one warp per batch ----------------
// Lane l owns columns j0=2l, j1=2l+1. Linear-space recursion with exact
// power-of-2 renorm:
//   a[t+1][j] = ( sum_i a[t][i] * E[i][j] ) * 2^(127-e) * exp(emit[t][j])
// E = exp(trans) in registers (64 packed f32x2 pairs). Per step: STS.64 +
// __syncwarp + 16 broadcast LDS.128 + 64 FFMA2. Refill = ONE coalesced
// emissions LDG + 2 off-chain MUFU exp. No labels, no trans gathers, no
// gold work here at all.
__global__ __launch_bounds__(32, 1)
void crf_forward_kernel(const float* __restrict__ emis,
                        const float* __restrict__ trans,
                        const float* __restrict__ start_t,
                        const float* __restrict__ end_t,
                        const int*  __restrict__ sent_len,
                        int T)
{
    const int b    = blockIdx.x;
    const int lane = threadIdx.x;
    const int j0   = 2 * lane;
    const int j1   = j0 + 1;
    const int L    = sent_len[b];
    const float* em = emis + (size_t)b * T * KDIM;

    __shared__ __align__(16) float sa[2][KDIM];

    // E pairs over i for the two owned columns: 64 ull = 128 regs
    ull Epk0[KDIM / 2], Epk1[KDIM / 2];
#pragma unroll
    for (int i2 = 0; i2 < KDIM / 2; ++i2) {
        const float a00 = __expf(trans[(2 * i2)     * KDIM + j0]);
        const float a10 = __expf(trans[(2 * i2 + 1) * KDIM + j0]);
        const float a01 = __expf(trans[(2 * i2)     * KDIM + j1]);
        const float a11 = __expf(trans[(2 * i2 + 1) * KDIM + j1]);
        Epk0[i2] = (ull)__float_as_uint(a00) | ((ull)__float_as_uint(a10) << 32);
        Epk1[i2] = (ull)__float_as_uint(a01) | ((ull)__float_as_uint(a11) << 32);
    }

    // t = 0
    const float2 st  = ((const float2*)start_t)[lane];
    const float2 em0 = ((const float2*)em)[lane];
    float ax = __expf(st.x + em0.x);
    float ay = __expf(st.y + em0.y);
    int   Stot = 0;

    // prefetch ring: P = exp(emissions) for steps t = 1..PF
    float2 Pr[PF];
#pragma unroll
    for (int k = 0; k < PF; ++k) {
        int tt = 1 + k; if (tt > T - 1) tt = T - 1;
        const float2 ee = ((const float2*)(em + (size_t)tt * KDIM))[lane];
        Pr[k] = make_float2(__expf(ee.x), __expf(ee.y));
    }

    int buf = 0;
    auto step = [&](float2 P) {
        const float piv = __shfl_sync(0xffffffffu, ax, 0);   // off-chain pivot
        ((float2*)sa[buf])[lane] = make_float2(ax, ay);
        __syncwarp();
        const int   e   = (int)((__float_as_uint(piv) >> 23) & 0xffu);
        const float scl = __uint_as_float((unsigned)(254 - e) << 23); // 2^(127-e)
        Stot += e - 127;
        ull b0 = 0ull, b1 = 0ull, b2 = 0ull, b3 = 0ull;
        ull c0 = 0ull, c1 = 0ull, c2 = 0ull, c3 = 0ull;
        const ulonglong2* sv = (const ulonglong2*)sa[buf];
#pragma unroll
        for (int q = 0; q < 8; ++q) {
            const ulonglong2 v0 = sv[2 * q];
            const ulonglong2 v1 = sv[2 * q + 1];
            fma2(b0, v0.x, Epk0[4 * q + 0]);  fma2(c0, v0.x, Epk1[4 * q + 0]);
            fma2(b1, v0.y, Epk0[4 * q + 1]);  fma2(c1, v0.y, Epk1[4 * q + 1]);
            fma2(b2, v1.x, Epk0[4 * q + 2]);  fma2(c2, v1.x, Epk1[4 * q + 2]);
            fma2(b3, v1.y, Epk0[4 * q + 3]);  fma2(c3, v1.y, Epk1[4 * q + 3]);
        }
        add2(b0, b0, b1); add2(b2, b2, b3); add2(b0, b0, b2);
        add2(c0, c0, c1); add2(c2, c2, c3); add2(c0, c0, c2);
        const float d0 = __uint_as_float((unsigned)b0)
                       + __uint_as_float((unsigned)(b0 >> 32));
        const float d1 = __uint_as_float((unsigned)c0)
                       + __uint_as_float((unsigned)(c0 >> 32));
        ax = d0 * scl * P.x;
        ay = d1 * scl * P.y;
        buf ^= 1;
    };

    int t = 1;
    for (; t + PF <= L; t += PF) {
#pragma unroll
        for (int k = 0; k < PF; ++k) {
            const float2 Pc = Pr[k];
            int tp = t + PF + k; if (tp > T - 1) tp = T - 1;
            const float2 ee = ((const float2*)(em + (size_t)tp * KDIM))[lane];
            Pr[k] = make_float2(__expf(ee.x), __expf(ee.y));
            step(Pc);
        }
    }
    for (int k = 0; t < L; ++t, ++k)       // tail: ring already filled
        step(Pr[k]);

    // fwd = log( sum_j a[j]*exp(end[j]) ) + Stot*ln2
    const float2 en = ((const float2*)end_t)[lane];
    float xs = ax * __expf(en.x) + ay * __expf(en.y);
#pragma unroll
    for (int o = 16; o; o >>= 1)
        xs += __shfl_xor_sync(0xffffffffu, xs, o);
    if (lane == 0)
        g_fwd[b] = __logf(xs) + (float)Stot * 0.69314718055994530942f;
}

// ---------------- final: out = sum(fwd - gold)/B ----------------
__global__ void crf_final_reduce(float* __restrict__ out, int B)
{
    __shared__ float ws[16];
    const int tid = threadIdx.x;
    float v = 0.0f;
    for (int i = tid; i < B; i += blockDim.x) v += g_fwd[i] - g_gold[i];
#pragma unroll
    for (int o = 16; o; o >>= 1) v += __shfl_xor_sync(0xffffffffu, v, o);
    if ((tid & 31) == 0) ws[tid >> 5] = v;
    __syncthreads();
    if (tid < 16) {
        float u = (tid < (blockDim.x + 31) / 32) ? ws[tid] : 0.0f;
#pragma unroll
        for (int o = 8; o; o >>= 1) u += __shfl_xor_sync(0x0000ffffu, u, o);
        if (tid == 0) out[0] = u / (float)B;
    }
}

extern "C" void kernel_launch(void* const* d_in, const int* in_sizes, int n_in,
                              void* d_out, int out_size)
{
    const float* emis    = (const float*)d_in[0];
    const float* trans   = (const float*)d_in[1];
    const float* start_t = (const float*)d_in[2];
    const float* end_t   = (const float*)d_in[3];
    const int*   labels  = (const int*)d_in[4];
    const int*   slen    = (const int*)d_in[5];

    const int B = in_sizes[5];            // 512
    const int T = in_sizes[4] / B;        // 1024
    float* out = (float*)d_out;

    crf_gold_prepass<<<(B * T + 255) / 256, 256>>>(emis, trans, start_t, labels, B, T);
    crf_gold_reduce<<<B / 8, 256>>>(end_t, labels, slen, T);
    crf_forward_kernel<<<B, 32>>>(emis, trans, start_t, end_t, slen, T);
    crf_final_reduce<<<1, 512>>>(out, B);
}

// round 9
// speedup vs baseline: 1.7736x; 1.0172x over previous
#include <cuda_runtime.h>
#include <cuda_bf16.h>

#define KDIM 64
#define PF   4   // prefetch depth (steps)

__device__ float g_partial[1024];
__device__ int   g_done = 0;

typedef unsigned long long ull;

__device__ __forceinline__ void fma2(ull& acc, ull a, ull b) {
    asm("fma.rn.f32x2 %0, %1, %2, %3;" : "=l"(acc) : "l"(a), "l"(b), "l"(acc));
}
__device__ __forceinline__ void add2(ull& d, ull a, ull b) {
    asm("add.rn.f32x2 %0, %1, %2;" : "=l"(d) : "l"(a), "l"(b));
}

// ONE warp per batch, ONE fused kernel (gold + forward + final reduction via
// atomic-counter finisher). Lane l owns columns j0=2l, j1=2l+1.
// Linear-space recursion, exact power-of-2 renorm:
//   a[t+1][j] = ( sum_i a[t][i] * E[i][j] ) * 2^(127-e) * exp(emit[t][j])
// E = exp(trans) in registers (64 packed f32x2 pairs).
// Per step: STS.64 + 16 broadcast LDS.128 + 64 FFMA2. No WARPSYNC (convergent
// warp: STS issues before LDS in program order; compiler barrier stops
// reordering). Renorm pivot = sa[0], reused from the first LDS.128 (no SHFL).
// Emissions/labels/gold-trans prefetched PF steps ahead.
__global__ __launch_bounds__(32, 1)
void crf_fused_kernel(const float* __restrict__ emis,
                      const float* __restrict__ trans,
                      const float* __restrict__ start_t,
                      const float* __restrict__ end_t,
                      const int*  __restrict__ labels,
                      const int*  __restrict__ sent_len,
                      int T, int B, float* __restrict__ out)
{
    const int b    = blockIdx.x;
    const int lane = threadIdx.x;
    const int j0   = 2 * lane;
    const int j1   = j0 + 1;
    const int L    = sent_len[b];
    const float* em  = emis   + (size_t)b * T * KDIM;
    const int*   lab = labels + (size_t)b * T;

    __shared__ __align__(16) float sa[2][KDIM];

    // E pairs over i for the two owned columns: 64 ull = 128 regs
    ull Epk0[KDIM / 2], Epk1[KDIM / 2];
#pragma unroll
    for (int i2 = 0; i2 < KDIM / 2; ++i2) {
        const float a00 = __expf(trans[(2 * i2)     * KDIM + j0]);
        const float a10 = __expf(trans[(2 * i2 + 1) * KDIM + j0]);
        const float a01 = __expf(trans[(2 * i2)     * KDIM + j1]);
        const float a11 = __expf(trans[(2 * i2 + 1) * KDIM + j1]);
        Epk0[i2] = (ull)__float_as_uint(a00) | ((ull)__float_as_uint(a10) << 32);
        Epk1[i2] = (ull)__float_as_uint(a01) | ((ull)__float_as_uint(a11) << 32);
    }

    // t = 0
    const float2 st  = ((const float2*)start_t)[lane];
    const float2 em0 = ((const float2*)em)[lane];
    const float l0x = st.x + em0.x;
    const float l0y = st.y + em0.y;
    float ax = __expf(l0x);
    float ay = __expf(l0y);
    int   Stot = 0;
    float gold_emit  = 0.0f;   // per-lane masked emission (+start/end) terms
    float gold_trans = 0.0f;   // uniform across lanes (broadcast tv)
    int   lab_last = lab[0];
    if (j0 == lab_last) gold_emit = l0x;
    if (j1 == lab_last) gold_emit = l0y;

    // prefetch rings for steps t = 1..PF
    float2 er[PF], Pr[PF];
    float  tvr[PF];
    int    lbr[PF];
    int lab_roll = lab_last;                  // lab[t-1] rolling value
#pragma unroll
    for (int k = 0; k < PF; ++k) {
        int tt = 1 + k; if (tt > T - 1) tt = T - 1;
        const float2 ee = ((const float2*)(em + (size_t)tt * KDIM))[lane];
        er[k] = ee;
        Pr[k] = make_float2(__expf(ee.x), __expf(ee.y));
        const int l1 = lab[tt];
        lbr[k] = l1;
        tvr[k] = trans[lab_roll * KDIM + l1];
        lab_roll = l1;
    }

    int buf = 0;
    auto step = [&](float2 P, float2 eraw, int labt, float tvv) {
        ((float2*)sa[buf])[lane] = make_float2(ax, ay);
        asm volatile("" ::: "memory");   // order STS before the LDS below
        // gold terms (registers only)
        if (j0 == labt) gold_emit += eraw.x;
        if (j1 == labt) gold_emit += eraw.y;
        gold_trans += tvv;
        lab_last = labt;
        const ulonglong2* sv = (const ulonglong2*)sa[buf];
        // first vector load also carries the pivot (sa[0] = low word of v00.x)
        const ulonglong2 v00 = sv[0];
        const ulonglong2 v01 = sv[1];
        const unsigned   pb  = (unsigned)v00.x;            // bits of sa[0]
        const int        e   = (int)((pb >> 23) & 0xffu);
        const float      scl = __uint_as_float((unsigned)(254 - e) << 23); // 2^(127-e)
        Stot += e - 127;
        ull b0 = 0ull, b1 = 0ull, b2 = 0ull, b3 = 0ull;
        ull c0 = 0ull, c1 = 0ull, c2 = 0ull, c3 = 0ull;
        fma2(b0, v00.x, Epk0[0]);  fma2(c0, v00.x, Epk1[0]);
        fma2(b1, v00.y, Epk0[1]);  fma2(c1, v00.y, Epk1[1]);
        fma2(b2, v01.x, Epk0[2]);  fma2(c2, v01.x, Epk1[2]);
        fma2(b3, v01.y, Epk0[3]);  fma2(c3, v01.y, Epk1[3]);
#pragma unroll
        for (int q = 1; q < 8; ++q) {
            const ulonglong2 v0 = sv[2 * q];
            const ulonglong2 v1 = sv[2 * q + 1];
            fma2(b0, v0.x, Epk0[4 * q + 0]);  fma2(c0, v0.x, Epk1[4 * q + 0]);
            fma2(b1, v0.y, Epk0[4 * q + 1]);  fma2(c1, v0.y, Epk1[4 * q + 1]);
            fma2(b2, v1.x, Epk0[4 * q + 2]);  fma2(c2, v1.x, Epk1[4 * q + 2]);
            fma2(b3, v1.y, Epk0[4 * q + 3]);  fma2(c3, v1.y, Epk1[4 * q + 3]);
        }
        add2(b0, b0, b1); add2(b2, b2, b3); add2(b0, b0, b2);
        add2(c0, c0, c1); add2(c2, c2, c3); add2(c0, c0, c2);
        const float d0 = __uint_as_float((unsigned)b0)
                       + __uint_as_float((unsigned)(b0 >> 32));
        const float d1 = __uint_as_float((unsigned)c0)
                       + __uint_as_float((unsigned)(c0 >> 32));
        ax = d0 * scl * P.x;
        ay = d1 * scl * P.y;
        buf ^= 1;
    };

    int t = 1;
    for (; t + PF <= L; t += PF) {
#pragma unroll
        for (int k = 0; k < PF; ++k) {
            const float2 Pc = Pr[k], ec = er[k];
            const float  tc = tvr[k];
            const int    lc = lbr[k];
            int tp = t + PF + k; if (tp > T - 1) tp = T - 1;
            const float2 ee = ((const float2*)(em + (size_t)tp * KDIM))[lane];
            er[k] = ee;
            Pr[k] = make_float2(__expf(ee.x), __expf(ee.y));
            const int l1 = lab[tp];
            lbr[k] = l1;
            tvr[k] = trans[lab_roll * KDIM + l1];   // unused if clamped
            lab_roll = l1;
            step(Pc, ec, lc, tc);
        }
    }
    for (int k = 0; t < L; ++t, ++k)       // tail: ring already filled
        step(Pr[k], er[k], lbr[k], tvr[k]);

    // gold end term + final per-batch logsumexp
    {
        const float2 en = ((const float2*)end_t)[lane];
        if (j0 == lab_last) gold_emit += en.x;
        if (j1 == lab_last) gold_emit += en.y;
        float xs = ax * __expf(en.x) + ay * __expf(en.y);
        float gg = gold_emit;
#pragma unroll
        for (int o = 16; o; o >>= 1) {
            xs += __shfl_xor_sync(0xffffffffu, xs, o);
            gg += __shfl_xor_sync(0xffffffffu, gg, o);
        }
        if (lane == 0) {
            const float fwd = __logf(xs) + (float)Stot * 0.69314718055994530942f;
            g_partial[b] = fwd - (gg + gold_trans);
        }
    }

    // ---- finisher: last block to arrive reduces all partials ----
    __threadfence();
    int isLast = 0;
    if (lane == 0) {
        const int old = atomicAdd(&g_done, 1);
        isLast = (old == B - 1);
    }
    isLast = __shfl_sync(0xffffffffu, isLast, 0);
    if (isLast) {
        __threadfence();                   // acquire: see all g_partial writes
        float v = 0.0f;
        for (int i = lane; i < B; i += 32) v += g_partial[i];
#pragma unroll
        for (int o = 16; o; o >>= 1) v += __shfl_xor_sync(0xffffffffu, v, o);
        if (lane == 0) {
            out[0] = v / (float)B;
            g_done = 0;                    // reset for next (deterministic) call
        }
    }
}

extern "C" void kernel_launch(void* const* d_in, const int* in_sizes, int n_in,
                              void* d_out, int out_size)
{
    const float* emis    = (const float*)d_in[0];
    const float* trans   = (const float*)d_in[1];
    const float* start_t = (const float*)d_in[2];
    const float* end_t   = (const float*)d_in[3];
    const int*   labels  = (const int*)d_in[4];
    const int*   slen    = (const int*)d_in[5];

    const int B = in_sizes[5];            // 512
    const int T = in_sizes[4] / B;        // 1024
    float* out = (float*)d_out;

    crf_fused_kernel<<<B, 32>>>(emis, trans, start_t, end_t, labels, slen, T, B, out);
}